// round 3
// baseline (speedup 1.0000x reference)
#include <cuda_runtime.h>

// Problem constants
#define TT   4096      // sequence length T
#define TM1  4095      // T-1 steps
#define EE   512       // embedding dim E
#define HH   1024      // hidden dim H
#define G4   4096      // 4*H
#define CC   1221      // output classes C
#define NCTA 128       // persistent CTAs for the recurrence

typedef unsigned long long u64;

#define CANARY 0x7fc0deadu   // qNaN payload: h = o*tanh(c) in (-1,1) can never equal it

// ---------------- scratch (static device globals; no allocation allowed) ----
__device__ float    g_emb[(size_t)TT * EE];        // gathered embeddings  (8 MB)
__device__ float    g_bias4h[G4];                  // b_ih + b_hh + last@W_ih[:,E:]
__device__ float    g_xg[(size_t)TM1 * G4];        // precomputed input gates (67 MB)
__device__ float    g_hs[(size_t)TM1 * HH];        // all hidden states (16.8 MB)

// ---------------- helpers ---------------------------------------------------
__device__ __forceinline__ u64 fma2(u64 a, u64 b, u64 c) {
    u64 d;
    asm("fma.rn.f32x2 %0, %1, %2, %3;" : "=l"(d) : "l"(a), "l"(b), "l"(c));
    return d;
}
__device__ __forceinline__ u64 pack2(float lo, float hi) {
    u64 r;
    asm("mov.b64 %0, {%1, %2};" : "=l"(r) : "f"(lo), "f"(hi));
    return r;
}
__device__ __forceinline__ float2 unpack2(u64 v) {
    float2 r;
    asm("mov.b64 {%0, %1}, %2;" : "=f"(r.x), "=f"(r.y) : "l"(v));
    return r;
}
__device__ __forceinline__ uint4 ld_vol4(const void* p) {
    uint4 v;
    asm volatile("ld.volatile.global.v4.u32 {%0,%1,%2,%3}, [%4];"
                 : "=r"(v.x), "=r"(v.y), "=r"(v.z), "=r"(v.w)
                 : "l"(p) : "memory");
    return v;
}
__device__ __forceinline__ void st_vol_f32(float* p, float x) {
    asm volatile("st.volatile.global.f32 [%0], %1;" :: "l"(p), "f"(x) : "memory");
}
__device__ __forceinline__ bool bad4(uint4 v) {
    return (v.x == CANARY) | (v.y == CANARY) | (v.z == CANARY) | (v.w == CANARY);
}
__device__ __forceinline__ float fast_sig(float x) {      // 1/(1+e^-x)
    return __fdividef(1.f, 1.f + __expf(-x));
}
__device__ __forceinline__ float fast_tanh(float x) {     // 2*sig(2x)-1
    return __fdividef(2.f, 1.f + __expf(-2.f * x)) - 1.f;
}

// ---------------- canary fill of g_hs (every launch) -------------------------
__global__ void k_canary() {
    size_t i = ((size_t)blockIdx.x * 256 + threadIdx.x) * 4;   // 4095*256*4 = TM1*HH
    uint4 c4 = make_uint4(CANARY, CANARY, CANARY, CANARY);
    *(uint4*)((unsigned*)g_hs + i) = c4;
}

// ---------------- embedding gather ------------------------------------------
__global__ void k_gather(const int* __restrict__ x, const float* __restrict__ tab) {
    int t = blockIdx.x;
    int row = x[t];
    float4 v = *(const float4*)(tab + (size_t)row * EE + threadIdx.x * 4);
    *(float4*)(g_emb + (size_t)t * EE + threadIdx.x * 4) = v;
}

// ---------------- bias vector: b_ih + b_hh + last_emb @ W_ih[:, E:].T --------
__global__ void k_bias(const float* __restrict__ W_ih,
                       const float* __restrict__ b_ih,
                       const float* __restrict__ b_hh) {
    int w = threadIdx.x >> 5, lane = threadIdx.x & 31;
    int g = blockIdx.x * 8 + w;
    const float* wrow = W_ih + (size_t)g * (2 * EE) + EE;
    const float* le   = g_emb + (size_t)(TT - 1) * EE;
    float s = 0.f;
#pragma unroll
    for (int i = 0; i < 4; i++) {
        float4 a = *(const float4*)(wrow + i * 128 + lane * 4);
        float4 b = *(const float4*)(le   + i * 128 + lane * 4);
        s += a.x * b.x + a.y * b.y + a.z * b.z + a.w * b.w;
    }
#pragma unroll
    for (int off = 16; off; off >>= 1) s += __shfl_xor_sync(0xffffffffu, s, off);
    if (lane == 0) g_bias4h[g] = s + b_ih[g] + b_hh[g];
}

// ---------------- SGEMM: C[M,N] = A[M,K] * B[N,K]^T + bias[n] ----------------
__device__ __forceinline__ void sgemm_body(
    const float* __restrict__ A, int lda,
    const float* __restrict__ B, int ldb,
    const float* __restrict__ bias,
    float* __restrict__ C, int ldc,
    int M, int N, int K)
{
    __shared__ __align__(16) float As[16][128];
    __shared__ __align__(16) float Bs[16][128];
    int tid = threadIdx.x;
    int tx = tid & 15, ty = tid >> 4;
    int row0 = blockIdx.y * 128, col0 = blockIdx.x * 128;

    u64 acc[8][4];
#pragma unroll
    for (int m = 0; m < 8; m++)
#pragma unroll
        for (int n2 = 0; n2 < 4; n2++) acc[m][n2] = 0ull;

    for (int k0 = 0; k0 < K; k0 += 16) {
#pragma unroll
        for (int li = tid; li < 512; li += 256) {
            int r = li >> 2, c4 = (li & 3) << 2;
            float4 v = make_float4(0.f, 0.f, 0.f, 0.f);
            int gr = row0 + r;
            if (gr < M) v = *(const float4*)(A + (size_t)gr * lda + k0 + c4);
            As[c4][r] = v.x; As[c4 + 1][r] = v.y; As[c4 + 2][r] = v.z; As[c4 + 3][r] = v.w;
            float4 wv = make_float4(0.f, 0.f, 0.f, 0.f);
            int gn = col0 + r;
            if (gn < N) wv = *(const float4*)(B + (size_t)gn * ldb + k0 + c4);
            Bs[c4][r] = wv.x; Bs[c4 + 1][r] = wv.y; Bs[c4 + 2][r] = wv.z; Bs[c4 + 3][r] = wv.w;
        }
        __syncthreads();
#pragma unroll
        for (int k = 0; k < 16; k++) {
            float4 a0 = *(const float4*)&As[k][ty * 8];
            float4 a1 = *(const float4*)&As[k][ty * 8 + 4];
            ulonglong2 b0 = *(const ulonglong2*)&Bs[k][tx * 8];
            ulonglong2 b1 = *(const ulonglong2*)&Bs[k][tx * 8 + 4];
            float av[8] = {a0.x, a0.y, a0.z, a0.w, a1.x, a1.y, a1.z, a1.w};
            u64 bv[4] = {b0.x, b0.y, b1.x, b1.y};
#pragma unroll
            for (int m = 0; m < 8; m++) {
                u64 am = pack2(av[m], av[m]);
#pragma unroll
                for (int n2 = 0; n2 < 4; n2++)
                    acc[m][n2] = fma2(am, bv[n2], acc[m][n2]);
            }
        }
        __syncthreads();
    }
#pragma unroll
    for (int m = 0; m < 8; m++) {
        int gr = row0 + ty * 8 + m;
        if (gr >= M) continue;
#pragma unroll
        for (int n2 = 0; n2 < 4; n2++) {
            float2 s = unpack2(acc[m][n2]);
            int gc = col0 + tx * 8 + n2 * 2;
            if (gc < N)     C[(size_t)gr * ldc + gc]     = s.x + bias[gc];
            if (gc + 1 < N) C[(size_t)gr * ldc + gc + 1] = s.y + bias[gc + 1];
        }
    }
}

__global__ __launch_bounds__(256) void k_sgemm_xg(const float* __restrict__ W_ih) {
    sgemm_body(g_emb, EE, W_ih, 2 * EE, g_bias4h, g_xg, G4, TM1, G4, EE);
}

__global__ __launch_bounds__(256) void k_sgemm_out(const float* __restrict__ W_out,
                                                   const float* __restrict__ b_out,
                                                   float* __restrict__ out) {
    sgemm_body(g_hs, HH, W_out, HH, b_out, out, CC, TM1, CC, HH);
}

// ---------------- persistent LSTM recurrence (pipelined dataflow) ------------
// 128 CTAs x 256 threads. CTA b owns j = b*8 + warp. W_hh rows in registers.
// h_{t-1} polled via NaN-canary dataflow; half-split named barriers overlap
// chunk-arrival with FMA on the first half; double-buffered smem h; all-lane
// activations (no broadcast shfls / divergence); 2-step xg prefetch.
__global__ __launch_bounds__(256, 1) void k_lstm(const float* __restrict__ W_hh) {
    __shared__ __align__(16) float h_s[2][HH];
    int tid = threadIdx.x;
    int w = tid >> 5, lane = tid & 31;
    int j = blockIdx.x * 8 + w;

    // This warp's W_hh rows in registers: 4 gates x 32 k per lane (f32x2 pairs)
    ulonglong2 wr[4][8];
#pragma unroll
    for (int g = 0; g < 4; g++) {
        const float* base = W_hh + (size_t)(g * HH + j) * HH + lane * 4;
#pragma unroll
        for (int i = 0; i < 8; i++)
            wr[g][i] = *(const ulonglong2*)(base + i * 128);
    }

    float c = 0.f;
    float xg_cur = 0.f, xg_nxt = 0.f;          // per-lane (lane<4 = gate lane)
    if (lane < 4) {
        xg_cur = g_xg[(size_t)0 * G4 + lane * HH + j];
        xg_nxt = g_xg[(size_t)1 * G4 + lane * HH + j];
    }

    for (int t = 0; t < TM1; t++) {
        float* buf = h_s[t & 1];

        // stage own 16B chunk of h_{t-1} (dual-slot pipelined canary poll)
        if (t == 0) {
            *(float4*)&buf[tid * 4] = make_float4(0.f, 0.f, 0.f, 0.f);
        } else {
            const void* src = g_hs + (size_t)(t - 1) * HH + tid * 4;
            uint4 v = ld_vol4(src);
            if (bad4(v)) {
                uint4 v2 = ld_vol4(src);
                for (;;) {
                    if (!bad4(v)) break;
                    v = v2;
                    v2 = ld_vol4(src);
                }
            }
            *(uint4*)&buf[tid * 4] = v;
        }

        // publish my half; consume half0 as soon as its 128 stagers arrived
        if (tid < 128) asm volatile("bar.arrive 1, 384;" ::: "memory");
        else           asm volatile("bar.arrive 2, 384;" ::: "memory");
        asm volatile("bar.sync 1, 384;" ::: "memory");

        u64 acc[4] = {0ull, 0ull, 0ull, 0ull};
#pragma unroll
        for (int i = 0; i < 4; i++) {                    // h[0..511]
            ulonglong2 h2 = *(const ulonglong2*)&buf[i * 128 + lane * 4];
#pragma unroll
            for (int g = 0; g < 4; g++) {
                acc[g] = fma2(wr[g][i].x, h2.x, acc[g]);
                acc[g] = fma2(wr[g][i].y, h2.y, acc[g]);
            }
        }
        asm volatile("bar.sync 2, 384;" ::: "memory");
#pragma unroll
        for (int i = 4; i < 8; i++) {                    // h[512..1023]
            ulonglong2 h2 = *(const ulonglong2*)&buf[i * 128 + lane * 4];
#pragma unroll
            for (int g = 0; g < 4; g++) {
                acc[g] = fma2(wr[g][i].x, h2.x, acc[g]);
                acc[g] = fma2(wr[g][i].y, h2.y, acc[g]);
            }
        }

        float r0, r1, r2, r3;
        { float2 s = unpack2(acc[0]); r0 = s.x + s.y; }
        { float2 s = unpack2(acc[1]); r1 = s.x + s.y; }
        { float2 s = unpack2(acc[2]); r2 = s.x + s.y; }
        { float2 s = unpack2(acc[3]); r3 = s.x + s.y; }

        // inject xg into the owning lane's partial (summed once by the reduce)
        r0 = (lane == 0) ? r0 + xg_cur : r0;
        r1 = (lane == 1) ? r1 + xg_cur : r1;
        r2 = (lane == 2) ? r2 + xg_cur : r2;
        r3 = (lane == 3) ? r3 + xg_cur : r3;

        // rotate xg prefetch (2 steps ahead; ~2 full steps of DRAM cover)
        xg_cur = xg_nxt;
        {
            int tn = t + 2; if (tn > TM1 - 1) tn = TM1 - 1;
            if (lane < 4) xg_nxt = g_xg[(size_t)tn * G4 + lane * HH + j];
        }

        // butterfly: afterwards EVERY lane holds all four full gate sums
#pragma unroll
        for (int off = 16; off; off >>= 1) {
            r0 += __shfl_xor_sync(0xffffffffu, r0, off);
            r1 += __shfl_xor_sync(0xffffffffu, r1, off);
            r2 += __shfl_xor_sync(0xffffffffu, r2, off);
            r3 += __shfl_xor_sync(0xffffffffu, r3, off);
        }

        // all-lane activations (identical values on every lane; no shfl/branch)
        float gi = fast_sig(r0);
        float gf = fast_sig(r1);
        float gg = fast_tanh(r2);
        float go = fast_sig(r3);
        c = gf * c + gi * gg;
        float hv = go * fast_tanh(c);
        if (lane == 0)
            st_vol_f32(g_hs + (size_t)t * HH + j, hv);   // publish h_t[j]
    }
}

// ---------------- launch ------------------------------------------------------
extern "C" void kernel_launch(void* const* d_in, const int* in_sizes, int n_in,
                              void* d_out, int out_size) {
    const int*   x     = (const int*)d_in[0];
    const float* table = (const float*)d_in[1];
    const float* W_ih  = (const float*)d_in[2];
    const float* W_hh  = (const float*)d_in[3];
    const float* b_ih  = (const float*)d_in[4];
    const float* b_hh  = (const float*)d_in[5];
    const float* W_out = (const float*)d_in[6];
    const float* b_out = (const float*)d_in[7];
    float* out = (float*)d_out;
    (void)in_sizes; (void)n_in; (void)out_size;

    k_canary<<<TM1, 256>>>();              // reset dataflow canaries (every launch)
    k_gather<<<TT, 128>>>(x, table);
    k_bias<<<G4 / 8, 256>>>(W_ih, b_ih, b_hh);
    {   // x_gates GEMM: M=4095, N=4096, K=512
        dim3 grid((G4 + 127) / 128, (TM1 + 127) / 128);
        k_sgemm_xg<<<grid, 256>>>(W_ih);
    }
    k_lstm<<<NCTA, 256>>>(W_hh);
    {   // output GEMM: M=4095, N=1221, K=1024
        dim3 grid((CC + 127) / 128, (TM1 + 127) / 128);
        k_sgemm_out<<<grid, 256>>>(W_out, b_out, out);
    }
}